// round 13
// baseline (speedup 1.0000x reference)
#include <cuda_runtime.h>
#include <cuda_bf16.h>
#include <cuda_fp16.h>
#include <cstdint>
#include <math.h>

#define B_ROWS 65536
#define D_IN   784
#define D_HID  512
#define D_LAT  256
#define N_CODES 256
#define N_PAD  896
#define KB_XC  2368           // 3*784=2352 padded to 37*64
#define KA_H   (2 * D_HID)    // 1024
#define KB_H   (3 * D_HID)    // 1536
#define KA_E   (2 * D_LAT)    // 512
#define KB_E   (3 * D_LAT)    // 768

typedef __nv_bfloat16 bf16;
typedef __nv_bfloat162 bf162;

// ---------------- scratch ----------------------------------------------------
__device__ bf16 g_h3 [(size_t)B_ROWS * KA_H];    // [hh|hl]
__device__ float g_enc[(size_t)B_ROWS * D_LAT];
__device__ bf16 g_e3 [(size_t)B_ROWS * KA_E];    // [eh|el]
__device__ float2 g_Sp[(size_t)B_ROWS * 2];      // cb0 block argmins
__device__ float g_S1[(size_t)B_ROWS * N_CODES]; // raw enc.cb1^T
__device__ __half g_d1[(size_t)B_ROWS * D_HID];  // decoder hidden fp16
__device__ bf16 g_We1b[(size_t)D_HID * KB_XC];   // [Wh|Wh|Wl|pad16]
__device__ bf16 g_We2b[(size_t)D_LAT * KB_H];
__device__ bf16 g_cb3 [2 * N_CODES * KB_E];      // [cb0 rows | cb1 rows]
__device__ __half g_W2b[(size_t)N_PAD * D_HID];  // Wd2^T fp16
__device__ float g_cnorm[2 * N_CODES];
__device__ float g_cb1T[N_CODES * D_LAT];
__device__ float g_T1 [N_CODES * N_CODES];       // cn1[j] + 2*cb0_i.cb1_j
__device__ float g_P0 [N_CODES * D_HID];         // cb0 @ Wd1
__device__ float g_P1 [N_CODES * D_HID];         // cb1 @ Wd1
__device__ double g_loss[3];

// ====================== PTX helpers ========================================
__device__ __forceinline__ uint32_t smem_u32(const void* p) {
    uint32_t a;
    asm("{ .reg .u64 t; cvta.to.shared.u64 t, %1; cvt.u32.u64 %0, t; }"
        : "=r"(a) : "l"(p));
    return a;
}
#define CP16(dst, src) \
    asm volatile("cp.async.cg.shared.global [%0], [%1], 16;" :: "r"(dst), "l"(src) : "memory")
#define CP_COMMIT() asm volatile("cp.async.commit_group;" ::: "memory")
#define CP_WAIT(n)  asm volatile("cp.async.wait_group %0;" :: "n"(n) : "memory")
#define STS128(dst, a, b, c, d) \
    asm volatile("st.shared.v4.b32 [%0], {%1,%2,%3,%4};" \
        :: "r"(dst), "r"(a), "r"(b), "r"(c), "r"(d) : "memory")

__device__ __forceinline__ void ldsm_x4(uint32_t* r, uint32_t addr) {
    asm volatile("ldmatrix.sync.aligned.m8n8.x4.shared.b16 {%0,%1,%2,%3}, [%4];"
        : "=r"(r[0]), "=r"(r[1]), "=r"(r[2]), "=r"(r[3]) : "r"(addr));
}
__device__ __forceinline__ void ldsm_x2(uint32_t* r, uint32_t addr) {
    asm volatile("ldmatrix.sync.aligned.m8n8.x2.shared.b16 {%0,%1}, [%2];"
        : "=r"(r[0]), "=r"(r[1]) : "r"(addr));
}
__device__ __forceinline__ void mma_bf16(float* c, const uint32_t* a, const uint32_t* b) {
    asm volatile("mma.sync.aligned.m16n8k16.row.col.f32.bf16.bf16.f32 "
        "{%0,%1,%2,%3}, {%4,%5,%6,%7}, {%8,%9}, {%0,%1,%2,%3};"
        : "+f"(c[0]), "+f"(c[1]), "+f"(c[2]), "+f"(c[3])
        : "r"(a[0]), "r"(a[1]), "r"(a[2]), "r"(a[3]), "r"(b[0]), "r"(b[1]));
}
__device__ __forceinline__ void mma_f16(float* c, const uint32_t* a, const uint32_t* b) {
    asm volatile("mma.sync.aligned.m16n8k16.row.col.f32.f16.f16.f32 "
        "{%0,%1,%2,%3}, {%4,%5,%6,%7}, {%8,%9}, {%0,%1,%2,%3};"
        : "+f"(c[0]), "+f"(c[1]), "+f"(c[2]), "+f"(c[3])
        : "r"(a[0]), "r"(a[1]), "r"(a[2]), "r"(a[3]), "r"(b[0]), "r"(b[1]));
}
__device__ __forceinline__ void split_bf16(float v, bf16& hi, bf16& lo) {
    hi = __float2bfloat16_rn(v);
    lo = __float2bfloat16_rn(v - __bfloat162float(hi));
}

// ---------------- prep kernels ---------------------------------------------
__global__ void init_k() {
    if (threadIdx.x < 3) g_loss[threadIdx.x] = 0.0;
}

// We1 [784,512] -> g_We1b [512, 2368] rows [Wh|Wh|Wl|0]
__global__ void prep_we1_k(const float* __restrict__ We1) {
    int idx = blockIdx.x * blockDim.x + threadIdx.x;
    if (idx < D_HID * D_IN) {
        int n = idx / D_IN, k = idx % D_IN;
        bf16 hi, lo; split_bf16(We1[(size_t)k * D_HID + n], hi, lo);
        bf16* R = g_We1b + (size_t)n * KB_XC;
        R[k] = hi; R[D_IN + k] = hi; R[2 * D_IN + k] = lo;
        if (k < 16) R[2352 + k] = __float2bfloat16(0.f);
    }
}

// merged: We2 bf16-3 (512 blocks) | Wd2 fp16-1 (1792 blocks)
#define NB_WE2 (D_LAT * D_HID / 256)     // 512
#define NB_WD2 (N_PAD * D_HID / 256)     // 1792
__global__ void prep_small_k(const float* __restrict__ We2,
                             const float* __restrict__ Wd2) {
    int b = blockIdx.x;
    if (b < NB_WE2) {
        int idx = b * 256 + threadIdx.x;
        int n = idx / D_HID, k = idx % D_HID;
        bf16 hi, lo; split_bf16(We2[(size_t)k * D_LAT + n], hi, lo);
        bf16* R = g_We2b + (size_t)n * KB_H;
        R[k] = hi; R[D_HID + k] = hi; R[2 * D_HID + k] = lo;
        return;
    }
    b -= NB_WE2;
    {
        int idx = b * 256 + threadIdx.x;
        int n = idx / D_HID, k = idx % D_HID;
        g_W2b[(size_t)n * D_HID + k] =
            (n < D_IN) ? __float2half_rn(Wd2[(size_t)k * D_IN + n])
                       : __float2half_rn(0.f);
    }
}

// codebooks -> g_cb3 (split) + cnorm + cb1 transpose
__global__ void prep_cb_k(const float* __restrict__ cb0,
                          const float* __restrict__ cb1) {
    __shared__ float red[8];
    int c = blockIdx.x >> 8;
    int n = blockIdx.x & 255;
    int k = threadIdx.x;
    const float* cb = c ? cb1 : cb0;
    float v = cb[(size_t)n * D_LAT + k];
    bf16 hi, lo; split_bf16(v, hi, lo);
    bf16* R = g_cb3 + ((size_t)c * N_CODES + n) * KB_E;
    R[k] = hi; R[D_LAT + k] = hi; R[2 * D_LAT + k] = lo;
    if (c) g_cb1T[k * N_CODES + n] = v;

    float s = v * v;
    int lane = k & 31, warp = k >> 5;
#pragma unroll
    for (int off = 16; off > 0; off >>= 1)
        s += __shfl_down_sync(0xffffffffu, s, off);
    if (lane == 0) red[warp] = s;
    __syncthreads();
    if (k == 0) {
        float t = 0.f;
#pragma unroll
        for (int i = 0; i < 8; i++) t += red[i];
        g_cnorm[c * N_CODES + n] = t;
    }
}

// T1[i,j] = cn1[j] + 2*dot(cb0_i, cb1_j)
__global__ void prep_T1_k(const float* __restrict__ cb0) {
    __shared__ float c0s[8][256];
    int j = threadIdx.x;
    int i0 = blockIdx.x * 8;
#pragma unroll
    for (int ii = 0; ii < 8; ii++)
        c0s[ii][j] = cb0[(size_t)(i0 + ii) * D_LAT + j];
    __syncthreads();
    float acc[8] = {0, 0, 0, 0, 0, 0, 0, 0};
    for (int k = 0; k < D_LAT; k++) {
        float bvv = g_cb1T[k * N_CODES + j];
#pragma unroll
        for (int ii = 0; ii < 8; ii++) acc[ii] = fmaf(c0s[ii][k], bvv, acc[ii]);
    }
    float cn1 = g_cnorm[N_CODES + j];
#pragma unroll
    for (int ii = 0; ii < 8; ii++)
        g_T1[(size_t)(i0 + ii) * N_CODES + j] = fmaf(2.f, acc[ii], cn1);
}

// P[i,n] = dot(cb_i, Wd1[:,n])
__global__ void prep_P_k(const float* __restrict__ cb0,
                         const float* __restrict__ cb1,
                         const float* __restrict__ Wd1) {
    __shared__ float cs[8][256];
    int cbi = blockIdx.x >> 5;
    int i0 = (blockIdx.x & 31) * 8;
    const float* cb = cbi ? cb1 : cb0;
    float* P = cbi ? g_P1 : g_P0;
    int tid = threadIdx.x;
#pragma unroll
    for (int t = 0; t < 4; t++) {
        int u = tid + t * 512;
        cs[u >> 8][u & 255] = cb[(size_t)(i0 + (u >> 8)) * D_LAT + (u & 255)];
    }
    __syncthreads();
    float acc[8] = {0, 0, 0, 0, 0, 0, 0, 0};
    for (int k = 0; k < D_LAT; k++) {
        float w = Wd1[(size_t)k * D_HID + tid];
#pragma unroll
        for (int ii = 0; ii < 8; ii++) acc[ii] = fmaf(cs[ii][k], w, acc[ii]);
    }
#pragma unroll
    for (int ii = 0; ii < 8; ii++)
        P[(size_t)(i0 + ii) * D_HID + tid] = acc[ii];
}

__global__ void finalize_k(float* __restrict__ out_loss) {
    double loss = g_loss[0] / ((double)B_ROWS * (double)D_IN)
                + 0.25 * ((g_loss[1] + g_loss[2]) / ((double)B_ROWS * (double)D_LAT));
    out_loss[0] = (float)loss;
}

// ---------------- universal split HMMA GEMM (3-stage pipeline) --------------
// CVT==1: A side is raw f32 x [B,784]; loader converts to the conceptual
// [xh(784)|xl(784)|xh(784)|0(16)] bf16 row on the fly (bit-identical split).
// EPI 1: +bias, relu -> bf16 split pair [h|l], row stride ldc
// EPI 2: +bias, tanh -> f32 store + sum((v-X)^2) into lossAcc
// EPI 3: +bias -> f32 (Cout) AND bf16 split pair (Cout2, 2*Nout)
// EPI 4: N=512 scores: blocks 0,1 argmin -> Cout; blocks 2,3 raw -> Cout2
#define HM 128
#define HK 64
#define PITCH 144
#define NSTAGE 3
#define TILE_B (HM * PITCH)
#define SMEM_HMMA (2 * NSTAGE * TILE_B)

template <int EPI, int NT, int DT, int CVT>
__global__ void __launch_bounds__(256)
hmma_k(const void* __restrict__ Av, const void* __restrict__ BTv,
       const float* __restrict__ aux, void* __restrict__ Cout,
       void* __restrict__ Cout2, int kA, int K, int Nout, int ldc,
       const float* __restrict__ X, double* __restrict__ lossAcc) {
    extern __shared__ char sm[];
    __shared__ float red[8];

    const int HN_T = 16 * NT;
    const int tid = threadIdx.x;
    const int wid = tid >> 5, lane = tid & 31;
    const int warp_m = wid >> 1, warp_n = wid & 1;
    const int m0 = blockIdx.y * HM, n0 = blockIdx.x * HN_T;
    const int NC = K / HK;

    const uint32_t smA = smem_u32(sm);
    const uint32_t smB = smA + NSTAGE * TILE_B;

    const int lrow = tid >> 3;
    const int lseg = (tid & 7) << 4;
    const size_t rsA = (size_t)kA * 2;
    const size_t rsB = (size_t)K * 2;
    const char* Ag = (const char*)Av + (size_t)m0 * rsA + (size_t)lrow * rsA + lseg;
    const char* Bg = (const char*)BTv + (size_t)n0 * rsB + (size_t)lrow * rsB + lseg;
    const uint32_t stoff = lrow * PITCH + lseg;
    const int kAb = kA * 2;
    const float* Xg = (CVT == 1)
        ? (const float*)Av + (size_t)(m0 + lrow) * D_IN : nullptr;

    const int a_row = (lane & 15);
    const int a_kb16 = (lane >> 4) << 4;
    const int b_row = (lane & 7) + ((lane >> 4) << 3);
    const int b_kb16 = ((lane >> 3) & 1) << 4;

    uint32_t a_sm[NSTAGE], b_sm[NSTAGE];
#pragma unroll
    for (int s = 0; s < NSTAGE; s++) {
        a_sm[s] = smA + s * TILE_B + (warp_m * 32 + a_row) * PITCH + a_kb16;
        b_sm[s] = smB + s * TILE_B + (warp_n * (NT * 8) + b_row) * PITCH + b_kb16;
    }

    float acc[2][NT][4];
#pragma unroll
    for (int i = 0; i < 2; i++)
#pragma unroll
        for (int j = 0; j < NT; j++)
#pragma unroll
            for (int t = 0; t < 4; t++) acc[i][j][t] = 0.f;

    // ---- A-tile fill for chunk c into buffer buf (CVT path) ----
    auto fill_a_cvt = [&](int c, int buf) {
        int p0 = c * HK + ((tid & 7) << 3);   // conceptual element pos
        uint32_t st = smA + buf * TILE_B + stoff;
        if (p0 >= 2352) {                      // zero pad granule
#pragma unroll
            for (int j = 0; j < 4; j++)
                STS128(st + j * 32 * PITCH, 0u, 0u, 0u, 0u);
            return;
        }
        int seg = (p0 >= 1568) ? 2 : (p0 >= 784 ? 1 : 0);
        int off = p0 - seg * D_IN;
        bool isLo = (seg == 1);
#pragma unroll
        for (int j = 0; j < 4; j++) {
            const float* xr = Xg + (size_t)j * 32 * D_IN + off;
            float4 a = __ldg((const float4*)xr);
            float4 b2 = __ldg((const float4*)(xr + 4));
            float vv[8] = {a.x, a.y, a.z, a.w, b2.x, b2.y, b2.z, b2.w};
            uint32_t pk[4];
#pragma unroll
            for (int e = 0; e < 4; e++) {
                bf16 h0 = __float2bfloat16_rn(vv[2 * e]);
                bf16 h1 = __float2bfloat16_rn(vv[2 * e + 1]);
                bf16 o0 = h0, o1 = h1;
                if (isLo) {
                    o0 = __float2bfloat16_rn(vv[2 * e] - __bfloat162float(h0));
                    o1 = __float2bfloat16_rn(vv[2 * e + 1] - __bfloat162float(h1));
                }
                bf162 pr; pr.x = o0; pr.y = o1;
                pk[e] = *(uint32_t*)&pr;
            }
            STS128(st + j * 32 * PITCH, pk[0], pk[1], pk[2], pk[3]);
        }
    };

#pragma unroll
    for (int s = 0; s < NSTAGE - 1; s++) {
        int koffB = s * (HK * 2);
        uint32_t bst = smB + s * TILE_B + stoff;
        if (CVT == 1) {
            fill_a_cvt(s, s);
        } else {
            int koffA = (koffB < kAb) ? koffB : koffB - kAb;
            uint32_t ast = smA + s * TILE_B + stoff;
#pragma unroll
            for (int j = 0; j < 4; j++)
                CP16(ast + j * 32 * PITCH, Ag + (size_t)j * 32 * rsA + koffA);
        }
#pragma unroll
        for (int j = 0; j < 4; j++)
            CP16(bst + j * 32 * PITCH, Bg + (size_t)j * 32 * rsB + koffB);
        CP_COMMIT();
    }

    int pf = NSTAGE - 1;
    for (int i = 0; i < NC; i++) {
        CP_WAIT(NSTAGE - 2);
        __syncthreads();

        if (pf < NC) {
            int buf = pf % NSTAGE;
            int koffB = pf * (HK * 2);
            uint32_t bst = smB + buf * TILE_B + stoff;
            if (CVT == 1) {
                fill_a_cvt(pf, buf);
            } else {
                int koffA = (koffB < kAb) ? koffB : koffB - kAb;
                uint32_t ast = smA + buf * TILE_B + stoff;
#pragma unroll
                for (int j = 0; j < 4; j++)
                    CP16(ast + j * 32 * PITCH, Ag + (size_t)j * 32 * rsA + koffA);
            }
#pragma unroll
            for (int j = 0; j < 4; j++)
                CP16(bst + j * 32 * PITCH, Bg + (size_t)j * 32 * rsB + koffB);
        }
        CP_COMMIT();
        pf++;

        int buf = i % NSTAGE;
#pragma unroll
        for (int ks = 0; ks < 4; ks++) {
            uint32_t af[2][4];
#pragma unroll
            for (int im = 0; im < 2; im++)
                ldsm_x4(af[im], a_sm[buf] + im * 16 * PITCH + ks * 32);
            uint32_t bfr[(NT + 1) / 2][4];
#pragma unroll
            for (int jp = 0; jp < NT / 2; jp++)
                ldsm_x4(bfr[jp], b_sm[buf] + jp * 16 * PITCH + ks * 32);
            if (NT & 1)
                ldsm_x2(bfr[NT / 2], b_sm[buf] + (NT - 1) * 8 * PITCH + ks * 32);
#pragma unroll
            for (int im = 0; im < 2; im++)
#pragma unroll
                for (int jn = 0; jn < NT; jn++) {
                    if (DT == 0)
                        mma_bf16(acc[im][jn], af[im], &bfr[jn >> 1][(jn & 1) * 2]);
                    else
                        mma_f16(acc[im][jn], af[im], &bfr[jn >> 1][(jn & 1) * 2]);
                }
        }
    }

    // ---- epilogue
    const int qr = lane >> 2, qc = (lane & 3) * 2;

    if (EPI == 4) {
        if (blockIdx.x < 2) {
            __syncthreads();
            float2* sMin = (float2*)sm;
            const float* cn = aux;
#pragma unroll
            for (int im = 0; im < 2; im++) {
#pragma unroll
                for (int h = 0; h < 2; h++) {
                    int row = warp_m * 32 + im * 16 + h * 8 + qr;
                    float bv = 3.4e38f; int bi = 0x7fffffff;
#pragma unroll
                    for (int jn = 0; jn < NT; jn++) {
#pragma unroll
                        for (int t = 0; t < 2; t++) {
                            int gn = n0 + warp_n * (NT * 8) + jn * 8 + qc + t;
                            float dv = fmaf(-2.f, acc[im][jn][h * 2 + t], __ldg(&cn[gn]));
                            if (dv < bv) { bv = dv; bi = gn; }
                        }
                    }
#pragma unroll
                    for (int off = 1; off < 4; off <<= 1) {
                        float ov = __shfl_xor_sync(0xffffffffu, bv, off);
                        int   oi = __shfl_xor_sync(0xffffffffu, bi, off);
                        if (ov < bv || (ov == bv && oi < bi)) { bv = ov; bi = oi; }
                    }
                    if ((lane & 3) == 0)
                        sMin[row * 2 + warp_n] = make_float2(bv, (float)bi);
                }
            }
            __syncthreads();
            if (tid < HM) {
                float2 c0 = sMin[tid * 2 + 0], c1 = sMin[tid * 2 + 1];
                float2 b = (c1.x < c0.x || (c1.x == c0.x && c1.y < c0.y)) ? c1 : c0;
                ((float2*)Cout)[(size_t)(m0 + tid) * 2 + blockIdx.x] = b;
            }
        } else {
            int colbase = n0 - 256;
#pragma unroll
            for (int im = 0; im < 2; im++) {
#pragma unroll
                for (int h = 0; h < 2; h++) {
                    int gm = m0 + warp_m * 32 + im * 16 + qr + h * 8;
#pragma unroll
                    for (int jn = 0; jn < NT; jn++) {
                        int col = colbase + warp_n * (NT * 8) + jn * 8 + qc;
                        *(float2*)((float*)Cout2 + (size_t)gm * 256 + col) =
                            make_float2(acc[im][jn][h * 2 + 0],
                                        acc[im][jn][h * 2 + 1]);
                    }
                }
            }
        }
        return;
    }

    float lsum = 0.f;
#pragma unroll
    for (int im = 0; im < 2; im++) {
#pragma unroll
        for (int h = 0; h < 2; h++) {
            int gm = m0 + warp_m * 32 + im * 16 + qr + h * 8;
#pragma unroll
            for (int jn = 0; jn < NT; jn++) {
                int gn = n0 + warp_n * (NT * 8) + jn * 8 + qc;
                float v0 = acc[im][jn][h * 2 + 0];
                float v1 = acc[im][jn][h * 2 + 1];
                if (EPI == 1) {
                    v0 = fmaxf(v0 + __ldg(&aux[gn]),     0.f);
                    v1 = fmaxf(v1 + __ldg(&aux[gn + 1]), 0.f);
                    bf16 h0, l0, h1, l1;
                    split_bf16(v0, h0, l0); split_bf16(v1, h1, l1);
                    bf16* Cr = (bf16*)Cout + (size_t)gm * ldc;
                    bf162 hp; hp.x = h0; hp.y = h1;
                    bf162 lp; lp.x = l0; lp.y = l1;
                    *(bf162*)(Cr + gn)        = hp;
                    *(bf162*)(Cr + Nout + gn) = lp;
                } else if (EPI == 2) {
                    v0 = tanhf(v0 + __ldg(&aux[gn]));
                    v1 = tanhf(v1 + __ldg(&aux[gn + 1]));
                    const float* Xr = X + (size_t)gm * Nout + gn;
                    float d0 = v0 - Xr[0], d1 = v1 - Xr[1];
                    lsum = fmaf(d0, d0, fmaf(d1, d1, lsum));
                    *(float2*)((float*)Cout + (size_t)gm * Nout + gn) =
                        make_float2(v0, v1);
                } else {  // EPI == 3
                    v0 += __ldg(&aux[gn]);
                    v1 += __ldg(&aux[gn + 1]);
                    *(float2*)((float*)Cout + (size_t)gm * Nout + gn) =
                        make_float2(v0, v1);
                    bf16 h0, l0, h1, l1;
                    split_bf16(v0, h0, l0); split_bf16(v1, h1, l1);
                    bf16* Cr = (bf16*)Cout2 + (size_t)gm * (2 * Nout);
                    bf162 hp; hp.x = h0; hp.y = h1;
                    bf162 lp; lp.x = l0; lp.y = l1;
                    *(bf162*)(Cr + gn)        = hp;
                    *(bf162*)(Cr + Nout + gn) = lp;
                }
            }
        }
    }

    if (EPI == 2) {
#pragma unroll
        for (int off = 16; off > 0; off >>= 1)
            lsum += __shfl_down_sync(0xffffffffu, lsum, off);
        if (lane == 0) red[wid] = lsum;
        __syncthreads();
        if (tid == 0) {
            float s = 0.f;
#pragma unroll
            for (int i = 0; i < 8; i++) s += red[i];
            atomicAdd(lossAcc, (double)s);
        }
    }
}

// ------------- combined VQ: argmin0 + argmin1 + commits + dec1 gather -------
__global__ void __launch_bounds__(256)
vq_k(const float2* __restrict__ Sp, const float* __restrict__ S1e,
     const float* __restrict__ T1, const float* __restrict__ enc,
     const float* __restrict__ P0, const float* __restrict__ P1,
     const float* __restrict__ bd1, __half* __restrict__ dout,
     float* __restrict__ idx_out, double* __restrict__ lossBase) {
    __shared__ float w0s[8], w1s[8];
    int warp = threadIdx.x >> 5, lane = threadIdx.x & 31;
    size_t m = (size_t)blockIdx.x * 8 + warp;

    float2 a0 = Sp[m * 2 + 0];
    float2 a1 = Sp[m * 2 + 1];
    float2 b0 = (a1.x < a0.x || (a1.x == a0.x && a1.y < a0.y)) ? a1 : a0;
    int i0 = (int)b0.y;
    float dmin0 = b0.x;

    const float* T1r = T1 + (size_t)i0 * N_CODES;
    const float* S1r = S1e + m * N_CODES;
    float bv = 3.4e38f; int bi = 0x7fffffff;
#pragma unroll
    for (int t = 0; t < 8; t++) {
        int j = t * 32 + lane;
        float dv = fmaf(-2.f, S1r[j], T1r[j]);
        if (dv < bv) { bv = dv; bi = j; }
    }
#pragma unroll
    for (int off = 16; off > 0; off >>= 1) {
        float ov = __shfl_down_sync(0xffffffffu, bv, off);
        int   oi = __shfl_down_sync(0xffffffffu, bi, off);
        if (ov < bv || (ov == bv && oi < bi)) { bv = ov; bi = oi; }
    }
    bi = __shfl_sync(0xffffffffu, bi, 0);
    bv = __shfl_sync(0xffffffffu, bv, 0);
    int i1 = bi;

    const float4* e4 = (const float4*)(enc + m * D_LAT);
    float4 u = e4[lane * 2], v = e4[lane * 2 + 1];
    float ss = u.x * u.x + u.y * u.y + u.z * u.z + u.w * u.w
             + v.x * v.x + v.y * v.y + v.z * v.z + v.w * v.w;
#pragma unroll
    for (int off = 16; off > 0; off >>= 1)
        ss += __shfl_down_sync(0xffffffffu, ss, off);

    if (lane == 0) {
        idx_out[m * 2 + 0] = (float)i0;
        idx_out[m * 2 + 1] = (float)i1;
        float c0v = ss + dmin0;
        w0s[warp] = c0v;
        w1s[warp] = c0v + bv;
    }

    const float4* p0 = (const float4*)(P0 + (size_t)i0 * D_HID);
    const float4* p1 = (const float4*)(P1 + (size_t)i1 * D_HID);
    const float4* bz = (const float4*)bd1;
    __half2* dd = (__half2*)(dout + m * D_HID);
#pragma unroll
    for (int t = 0; t < 4; t++) {
        int n4 = t * 32 + lane;
        float4 xa = p0[n4], xb = p1[n4], xc = __ldg(&bz[n4]);
        float r0 = fmaxf(xa.x + xb.x + xc.x, 0.f);
        float r1 = fmaxf(xa.y + xb.y + xc.y, 0.f);
        float r2 = fmaxf(xa.z + xb.z + xc.z, 0.f);
        float r3 = fmaxf(xa.w + xb.w + xc.w, 0.f);
        __half2 h0; h0.x = __float2half_rn(r0); h0.y = __float2half_rn(r1);
        __half2 h1; h1.x = __float2half_rn(r2); h1.y = __float2half_rn(r3);
        dd[n4 * 2 + 0] = h0;
        dd[n4 * 2 + 1] = h1;
    }

    __syncthreads();
    if (threadIdx.x == 0) {
        float s0 = 0.f, s1 = 0.f;
#pragma unroll
        for (int i = 0; i < 8; i++) { s0 += w0s[i]; s1 += w1s[i]; }
        atomicAdd(lossBase + 1, (double)s0);
        atomicAdd(lossBase + 2, (double)s1);
    }
}

// ---------------- launch ----------------------------------------------------
extern "C" void kernel_launch(void* const* d_in, const int* in_sizes, int n_in,
                              void* d_out, int out_size) {
    const float* x   = (const float*)d_in[0];
    const float* We1 = (const float*)d_in[1];
    const float* be1 = (const float*)d_in[2];
    const float* We2 = (const float*)d_in[3];
    const float* be2 = (const float*)d_in[4];
    const float* cb0 = (const float*)d_in[5];
    const float* cb1 = (const float*)d_in[6];
    const float* Wd1 = (const float*)d_in[7];
    const float* bd1 = (const float*)d_in[8];
    const float* Wd2 = (const float*)d_in[9];
    const float* bd2 = (const float*)d_in[10];

    float* out       = (float*)d_out;
    float* out_recon = out;
    float* out_idx   = out + (size_t)B_ROWS * D_IN;
    float* out_loss  = out + (size_t)B_ROWS * D_IN + (size_t)B_ROWS * 2;

    bf16 *ph3, *pe3, *pWe1b, *pWe2b, *pcb3;
    __half *pd1, *pW2b;
    float *penc, *pcn, *pS1, *pT1, *pP0, *pP1;
    float2* pSp;
    double* pl;
    cudaGetSymbolAddress((void**)&ph3,   g_h3);
    cudaGetSymbolAddress((void**)&penc,  g_enc);
    cudaGetSymbolAddress((void**)&pe3,   g_e3);
    cudaGetSymbolAddress((void**)&pSp,   g_Sp);
    cudaGetSymbolAddress((void**)&pS1,   g_S1);
    cudaGetSymbolAddress((void**)&pd1,   g_d1);
    cudaGetSymbolAddress((void**)&pWe1b, g_We1b);
    cudaGetSymbolAddress((void**)&pWe2b, g_We2b);
    cudaGetSymbolAddress((void**)&pcb3,  g_cb3);
    cudaGetSymbolAddress((void**)&pW2b,  g_W2b);
    cudaGetSymbolAddress((void**)&pcn,   g_cnorm);
    cudaGetSymbolAddress((void**)&pT1,   g_T1);
    cudaGetSymbolAddress((void**)&pP0,   g_P0);
    cudaGetSymbolAddress((void**)&pP1,   g_P1);
    cudaGetSymbolAddress((void**)&pl,    g_loss);

    cudaFuncSetAttribute((const void*)hmma_k<1, 8, 0, 1>, cudaFuncAttributeMaxDynamicSharedMemorySize, SMEM_HMMA);
    cudaFuncSetAttribute((const void*)hmma_k<3, 8, 0, 0>, cudaFuncAttributeMaxDynamicSharedMemorySize, SMEM_HMMA);
    cudaFuncSetAttribute((const void*)hmma_k<4, 8, 0, 0>, cudaFuncAttributeMaxDynamicSharedMemorySize, SMEM_HMMA);
    cudaFuncSetAttribute((const void*)hmma_k<2, 7, 1, 0>, cudaFuncAttributeMaxDynamicSharedMemorySize, SMEM_HMMA);

    dim3 blk(256);

    init_k<<<1, 32>>>();
    prep_we1_k<<<(D_HID * D_IN + 255) / 256, 256>>>(We1);
    prep_small_k<<<NB_WE2 + NB_WD2, 256>>>(We2, Wd2);
    prep_cb_k<<<512, 256>>>(cb0, cb1);
    prep_T1_k<<<32, 256>>>(cb0);
    prep_P_k<<<64, 512>>>(cb0, cb1, Wd1);

    // encoder GEMM1: fused x-split loader (CVT), K = 2368
    hmma_k<1, 8, 0, 1><<<dim3(D_HID / 128, B_ROWS / HM), blk, SMEM_HMMA>>>(
        x, pWe1b, be1, ph3, nullptr, 0, KB_XC, D_HID, KA_H, nullptr, nullptr);
    hmma_k<3, 8, 0, 0><<<dim3(D_LAT / 128, B_ROWS / HM), blk, SMEM_HMMA>>>(
        ph3, pWe2b, be2, penc, pe3, KA_H, KB_H, D_LAT, 0, nullptr, nullptr);

    // combined score GEMM over [cb0|cb1]: argmin blocks + raw S1
    hmma_k<4, 8, 0, 0><<<dim3(512 / 128, B_ROWS / HM), blk, SMEM_HMMA>>>(
        pe3, pcb3, pcn, pSp, pS1, KA_E, KB_E, 512, 0, nullptr, nullptr);

    // combined VQ + dec1 gather
    vq_k<<<B_ROWS / 8, 256>>>(pSp, pS1, pT1, penc, pP0, pP1, bd1,
                              pd1, out_idx, pl);

    // dec2 (fp16-1)
    hmma_k<2, 7, 1, 0><<<dim3(D_IN / 112, B_ROWS / HM), blk, SMEM_HMMA>>>(
        pd1, pW2b, bd2, out_recon, nullptr, D_HID, D_HID, D_IN, 0, x, pl + 0);

    finalize_k<<<1, 1>>>(out_loss);
}

// round 14
// speedup vs baseline: 1.1093x; 1.1093x over previous
#include <cuda_runtime.h>
#include <cuda_bf16.h>
#include <cuda_fp16.h>
#include <cstdint>
#include <math.h>

#define B_ROWS 65536
#define D_IN   784
#define D_HID  512
#define D_LAT  256
#define N_CODES 256
#define N_PAD  896
#define KB_XC  2368           // [xh|xl|xh|pad16] : 3*784=2352 padded to 37*64
#define KA_H   (2 * D_HID)    // 1024
#define KB_H   (3 * D_HID)    // 1536
#define KA_E   (2 * D_LAT)    // 512
#define KB_E   (3 * D_LAT)    // 768

typedef __nv_bfloat16 bf16;
typedef __nv_bfloat162 bf162;

// ---------------- scratch ----------------------------------------------------
__device__ bf16 g_x3 [(size_t)B_ROWS * KB_XC];   // [xh|xl|xh|0]
__device__ bf16 g_h3 [(size_t)B_ROWS * KA_H];    // [hh|hl]
__device__ float g_enc[(size_t)B_ROWS * D_LAT];
__device__ bf16 g_e3 [(size_t)B_ROWS * KA_E];    // [eh|el]
__device__ float2 g_Sp[(size_t)B_ROWS * 2];      // cb0 block argmins
__device__ float g_S1[(size_t)B_ROWS * N_CODES]; // raw enc.cb1^T
__device__ __half g_d1[(size_t)B_ROWS * D_HID];  // decoder hidden fp16
__device__ bf16 g_We1b[(size_t)D_HID * KB_XC];   // [Wh|Wh|Wl|pad16]
__device__ bf16 g_We2b[(size_t)D_LAT * KB_H];
__device__ bf16 g_cb3 [2 * N_CODES * KB_E];      // [cb0 rows | cb1 rows]
__device__ __half g_W2b[(size_t)N_PAD * D_HID];  // Wd2^T fp16
__device__ float g_cnorm[2 * N_CODES];
__device__ float g_cb1T[N_CODES * D_LAT];
__device__ float g_T1 [N_CODES * N_CODES];       // cn1[j] + 2*cb0_i.cb1_j
__device__ float g_P0 [N_CODES * D_HID];         // cb0 @ Wd1
__device__ float g_P1 [N_CODES * D_HID];         // cb1 @ Wd1
__device__ double g_loss[3];

// ====================== PTX helpers ========================================
__device__ __forceinline__ uint32_t smem_u32(const void* p) {
    uint32_t a;
    asm("{ .reg .u64 t; cvta.to.shared.u64 t, %1; cvt.u32.u64 %0, t; }"
        : "=r"(a) : "l"(p));
    return a;
}
#define CP16(dst, src) \
    asm volatile("cp.async.cg.shared.global [%0], [%1], 16;" :: "r"(dst), "l"(src) : "memory")
#define CP_COMMIT() asm volatile("cp.async.commit_group;" ::: "memory")
#define CP_WAIT(n)  asm volatile("cp.async.wait_group %0;" :: "n"(n) : "memory")

__device__ __forceinline__ void ldsm_x4(uint32_t* r, uint32_t addr) {
    asm volatile("ldmatrix.sync.aligned.m8n8.x4.shared.b16 {%0,%1,%2,%3}, [%4];"
        : "=r"(r[0]), "=r"(r[1]), "=r"(r[2]), "=r"(r[3]) : "r"(addr));
}
__device__ __forceinline__ void ldsm_x2(uint32_t* r, uint32_t addr) {
    asm volatile("ldmatrix.sync.aligned.m8n8.x2.shared.b16 {%0,%1}, [%2];"
        : "=r"(r[0]), "=r"(r[1]) : "r"(addr));
}
__device__ __forceinline__ void mma_bf16(float* c, const uint32_t* a, const uint32_t* b) {
    asm volatile("mma.sync.aligned.m16n8k16.row.col.f32.bf16.bf16.f32 "
        "{%0,%1,%2,%3}, {%4,%5,%6,%7}, {%8,%9}, {%0,%1,%2,%3};"
        : "+f"(c[0]), "+f"(c[1]), "+f"(c[2]), "+f"(c[3])
        : "r"(a[0]), "r"(a[1]), "r"(a[2]), "r"(a[3]), "r"(b[0]), "r"(b[1]));
}
__device__ __forceinline__ void mma_f16(float* c, const uint32_t* a, const uint32_t* b) {
    asm volatile("mma.sync.aligned.m16n8k16.row.col.f32.f16.f16.f32 "
        "{%0,%1,%2,%3}, {%4,%5,%6,%7}, {%8,%9}, {%0,%1,%2,%3};"
        : "+f"(c[0]), "+f"(c[1]), "+f"(c[2]), "+f"(c[3])
        : "r"(a[0]), "r"(a[1]), "r"(a[2]), "r"(a[3]), "r"(b[0]), "r"(b[1]));
}
__device__ __forceinline__ void split_bf16(float v, bf16& hi, bf16& lo) {
    hi = __float2bfloat16_rn(v);
    lo = __float2bfloat16_rn(v - __bfloat162float(hi));
}

// ---------------- prep kernels ---------------------------------------------
__global__ void init_k() {
    if (threadIdx.x < 3) g_loss[threadIdx.x] = 0.0;
}

// x [B,784] f32 -> g_x3 [B,2368] = [xh|xl|xh|0]
__global__ void prep_x_k(const float* __restrict__ x) {
    size_t idx = (size_t)blockIdx.x * blockDim.x + threadIdx.x;
    if (idx >= (size_t)B_ROWS * (D_IN / 4)) return;
    size_t m = idx / (D_IN / 4);
    int c = (int)(idx % (D_IN / 4)) * 4;
    float4 v = *(const float4*)(x + m * D_IN + c);
    bf16 h0, l0, h1, l1, h2, l2, h3, l3;
    split_bf16(v.x, h0, l0); split_bf16(v.y, h1, l1);
    split_bf16(v.z, h2, l2); split_bf16(v.w, h3, l3);
    bf162 hp0; hp0.x = h0; hp0.y = h1;
    bf162 hp1; hp1.x = h2; hp1.y = h3;
    bf162 lp0; lp0.x = l0; lp0.y = l1;
    bf162 lp1; lp1.x = l2; lp1.y = l3;
    bf162* R = (bf162*)(g_x3 + m * KB_XC);
    R[c / 2] = hp0;                  R[c / 2 + 1] = hp1;
    R[(D_IN + c) / 2] = lp0;         R[(D_IN + c) / 2 + 1] = lp1;
    R[(2 * D_IN + c) / 2] = hp0;     R[(2 * D_IN + c) / 2 + 1] = hp1;
    if (c == 0) {  // zero the 16-element pad
        bf162 z; z.x = __float2bfloat16(0.f); z.y = z.x;
#pragma unroll
        for (int t = 0; t < 8; t++) R[(3 * D_IN) / 2 + t] = z;
    }
}

// We1 [784,512] -> g_We1b [512, 2368] rows [Wh|Wh|Wl|0]
__global__ void prep_we1_k(const float* __restrict__ We1) {
    int idx = blockIdx.x * blockDim.x + threadIdx.x;
    if (idx < D_HID * D_IN) {
        int n = idx / D_IN, k = idx % D_IN;
        bf16 hi, lo; split_bf16(We1[(size_t)k * D_HID + n], hi, lo);
        bf16* R = g_We1b + (size_t)n * KB_XC;
        R[k] = hi; R[D_IN + k] = hi; R[2 * D_IN + k] = lo;
        if (k < 16) R[2352 + k] = __float2bfloat16(0.f);
    }
}

// merged: We2 bf16-3 (512 blocks) | Wd2 fp16-1 (1792 blocks)
#define NB_WE2 (D_LAT * D_HID / 256)     // 512
#define NB_WD2 (N_PAD * D_HID / 256)     // 1792
__global__ void prep_small_k(const float* __restrict__ We2,
                             const float* __restrict__ Wd2) {
    int b = blockIdx.x;
    if (b < NB_WE2) {
        int idx = b * 256 + threadIdx.x;
        int n = idx / D_HID, k = idx % D_HID;
        bf16 hi, lo; split_bf16(We2[(size_t)k * D_LAT + n], hi, lo);
        bf16* R = g_We2b + (size_t)n * KB_H;
        R[k] = hi; R[D_HID + k] = hi; R[2 * D_HID + k] = lo;
        return;
    }
    b -= NB_WE2;
    {
        int idx = b * 256 + threadIdx.x;
        int n = idx / D_HID, k = idx % D_HID;
        g_W2b[(size_t)n * D_HID + k] =
            (n < D_IN) ? __float2half_rn(Wd2[(size_t)k * D_IN + n])
                       : __float2half_rn(0.f);
    }
}

// codebooks -> g_cb3 (split) + cnorm + cb1 transpose
__global__ void prep_cb_k(const float* __restrict__ cb0,
                          const float* __restrict__ cb1) {
    __shared__ float red[8];
    int c = blockIdx.x >> 8;
    int n = blockIdx.x & 255;
    int k = threadIdx.x;
    const float* cb = c ? cb1 : cb0;
    float v = cb[(size_t)n * D_LAT + k];
    bf16 hi, lo; split_bf16(v, hi, lo);
    bf16* R = g_cb3 + ((size_t)c * N_CODES + n) * KB_E;
    R[k] = hi; R[D_LAT + k] = hi; R[2 * D_LAT + k] = lo;
    if (c) g_cb1T[k * N_CODES + n] = v;

    float s = v * v;
    int lane = k & 31, warp = k >> 5;
#pragma unroll
    for (int off = 16; off > 0; off >>= 1)
        s += __shfl_down_sync(0xffffffffu, s, off);
    if (lane == 0) red[warp] = s;
    __syncthreads();
    if (k == 0) {
        float t = 0.f;
#pragma unroll
        for (int i = 0; i < 8; i++) t += red[i];
        g_cnorm[c * N_CODES + n] = t;
    }
}

// T1[i,j] = cn1[j] + 2*dot(cb0_i, cb1_j)
__global__ void prep_T1_k(const float* __restrict__ cb0) {
    __shared__ float c0s[8][256];
    int j = threadIdx.x;
    int i0 = blockIdx.x * 8;
#pragma unroll
    for (int ii = 0; ii < 8; ii++)
        c0s[ii][j] = cb0[(size_t)(i0 + ii) * D_LAT + j];
    __syncthreads();
    float acc[8] = {0, 0, 0, 0, 0, 0, 0, 0};
    for (int k = 0; k < D_LAT; k++) {
        float bvv = g_cb1T[k * N_CODES + j];
#pragma unroll
        for (int ii = 0; ii < 8; ii++) acc[ii] = fmaf(c0s[ii][k], bvv, acc[ii]);
    }
    float cn1 = g_cnorm[N_CODES + j];
#pragma unroll
    for (int ii = 0; ii < 8; ii++)
        g_T1[(size_t)(i0 + ii) * N_CODES + j] = fmaf(2.f, acc[ii], cn1);
}

// P[i,n] = dot(cb_i, Wd1[:,n])
__global__ void prep_P_k(const float* __restrict__ cb0,
                         const float* __restrict__ cb1,
                         const float* __restrict__ Wd1) {
    __shared__ float cs[8][256];
    int cbi = blockIdx.x >> 5;
    int i0 = (blockIdx.x & 31) * 8;
    const float* cb = cbi ? cb1 : cb0;
    float* P = cbi ? g_P1 : g_P0;
    int tid = threadIdx.x;
#pragma unroll
    for (int t = 0; t < 4; t++) {
        int u = tid + t * 512;
        cs[u >> 8][u & 255] = cb[(size_t)(i0 + (u >> 8)) * D_LAT + (u & 255)];
    }
    __syncthreads();
    float acc[8] = {0, 0, 0, 0, 0, 0, 0, 0};
    for (int k = 0; k < D_LAT; k++) {
        float w = Wd1[(size_t)k * D_HID + tid];
#pragma unroll
        for (int ii = 0; ii < 8; ii++) acc[ii] = fmaf(cs[ii][k], w, acc[ii]);
    }
#pragma unroll
    for (int ii = 0; ii < 8; ii++)
        P[(size_t)(i0 + ii) * D_HID + tid] = acc[ii];
}

__global__ void finalize_k(float* __restrict__ out_loss) {
    double loss = g_loss[0] / ((double)B_ROWS * (double)D_IN)
                + 0.25 * ((g_loss[1] + g_loss[2]) / ((double)B_ROWS * (double)D_LAT));
    out_loss[0] = (float)loss;
}

// ---------------- universal split HMMA GEMM (3-stage pipeline) --------------
// C[M,N] = A[M,kA] @ BT[N,K]^T, K-remap on A (wraps when K > kA).
// EPI 1: +bias, relu -> bf16 split pair [h|l], row stride ldc
// EPI 2: +bias, tanh -> f32 store + sum((v-X)^2) into lossAcc
// EPI 3: +bias -> f32 (Cout) AND bf16 split pair (Cout2, 2*Nout)
// EPI 4: N=512 scores: blocks 0,1 argmin -> Cout; blocks 2,3 raw -> Cout2
#define HM 128
#define HK 64
#define PITCH 144
#define NSTAGE 3
#define TILE_B (HM * PITCH)
#define SMEM_HMMA (2 * NSTAGE * TILE_B)

template <int EPI, int NT, int DT>
__global__ void __launch_bounds__(256)
hmma_k(const void* __restrict__ Av, const void* __restrict__ BTv,
       const float* __restrict__ aux, void* __restrict__ Cout,
       void* __restrict__ Cout2, int kA, int K, int Nout, int ldc,
       const float* __restrict__ X, double* __restrict__ lossAcc) {
    extern __shared__ char sm[];
    __shared__ float red[8];

    const int HN_T = 16 * NT;
    const int tid = threadIdx.x;
    const int wid = tid >> 5, lane = tid & 31;
    const int warp_m = wid >> 1, warp_n = wid & 1;
    const int m0 = blockIdx.y * HM, n0 = blockIdx.x * HN_T;
    const int NC = K / HK;

    const uint32_t smA = smem_u32(sm);
    const uint32_t smB = smA + NSTAGE * TILE_B;

    const int lrow = tid >> 3;
    const int lseg = (tid & 7) << 4;
    const size_t rsA = (size_t)kA * 2;
    const size_t rsB = (size_t)K * 2;
    const char* Ag = (const char*)Av + (size_t)m0 * rsA + (size_t)lrow * rsA + lseg;
    const char* Bg = (const char*)BTv + (size_t)n0 * rsB + (size_t)lrow * rsB + lseg;
    const uint32_t stoff = lrow * PITCH + lseg;
    const int kAb = kA * 2;

    const int a_row = (lane & 15);
    const int a_kb16 = (lane >> 4) << 4;
    const int b_row = (lane & 7) + ((lane >> 4) << 3);
    const int b_kb16 = ((lane >> 3) & 1) << 4;

    uint32_t a_sm[NSTAGE], b_sm[NSTAGE];
#pragma unroll
    for (int s = 0; s < NSTAGE; s++) {
        a_sm[s] = smA + s * TILE_B + (warp_m * 32 + a_row) * PITCH + a_kb16;
        b_sm[s] = smB + s * TILE_B + (warp_n * (NT * 8) + b_row) * PITCH + b_kb16;
    }

    float acc[2][NT][4];
#pragma unroll
    for (int i = 0; i < 2; i++)
#pragma unroll
        for (int j = 0; j < NT; j++)
#pragma unroll
            for (int t = 0; t < 4; t++) acc[i][j][t] = 0.f;

#pragma unroll
    for (int s = 0; s < NSTAGE - 1; s++) {
        int koffB = s * (HK * 2);
        int koffA = (koffB < kAb) ? koffB : koffB - kAb;
        uint32_t ast = smA + s * TILE_B + stoff;
        uint32_t bst = smB + s * TILE_B + stoff;
#pragma unroll
        for (int j = 0; j < 4; j++) {
            CP16(ast + j * 32 * PITCH, Ag + (size_t)j * 32 * rsA + koffA);
            CP16(bst + j * 32 * PITCH, Bg + (size_t)j * 32 * rsB + koffB);
        }
        CP_COMMIT();
    }

    int pf = NSTAGE - 1;
    for (int i = 0; i < NC; i++) {
        CP_WAIT(NSTAGE - 2);
        __syncthreads();

        if (pf < NC) {
            int buf = pf % NSTAGE;
            int koffB = pf * (HK * 2);
            int koffA = (koffB < kAb) ? koffB : koffB - kAb;
            uint32_t ast = smA + buf * TILE_B + stoff;
            uint32_t bst = smB + buf * TILE_B + stoff;
#pragma unroll
            for (int j = 0; j < 4; j++) {
                CP16(ast + j * 32 * PITCH, Ag + (size_t)j * 32 * rsA + koffA);
                CP16(bst + j * 32 * PITCH, Bg + (size_t)j * 32 * rsB + koffB);
            }
        }
        CP_COMMIT();
        pf++;

        int buf = i % NSTAGE;
#pragma unroll
        for (int ks = 0; ks < 4; ks++) {
            uint32_t af[2][4];
#pragma unroll
            for (int im = 0; im < 2; im++)
                ldsm_x4(af[im], a_sm[buf] + im * 16 * PITCH + ks * 32);
            uint32_t bfr[(NT + 1) / 2][4];
#pragma unroll
            for (int jp = 0; jp < NT / 2; jp++)
                ldsm_x4(bfr[jp], b_sm[buf] + jp * 16 * PITCH + ks * 32);
            if (NT & 1)
                ldsm_x2(bfr[NT / 2], b_sm[buf] + (NT - 1) * 8 * PITCH + ks * 32);
#pragma unroll
            for (int im = 0; im < 2; im++)
#pragma unroll
                for (int jn = 0; jn < NT; jn++) {
                    if (DT == 0)
                        mma_bf16(acc[im][jn], af[im], &bfr[jn >> 1][(jn & 1) * 2]);
                    else
                        mma_f16(acc[im][jn], af[im], &bfr[jn >> 1][(jn & 1) * 2]);
                }
        }
    }

    // ---- epilogue
    const int qr = lane >> 2, qc = (lane & 3) * 2;

    if (EPI == 4) {
        if (blockIdx.x < 2) {
            __syncthreads();
            float2* sMin = (float2*)sm;
            const float* cn = aux;
#pragma unroll
            for (int im = 0; im < 2; im++) {
#pragma unroll
                for (int h = 0; h < 2; h++) {
                    int row = warp_m * 32 + im * 16 + h * 8 + qr;
                    float bv = 3.4e38f; int bi = 0x7fffffff;
#pragma unroll
                    for (int jn = 0; jn < NT; jn++) {
#pragma unroll
                        for (int t = 0; t < 2; t++) {
                            int gn = n0 + warp_n * (NT * 8) + jn * 8 + qc + t;
                            float dv = fmaf(-2.f, acc[im][jn][h * 2 + t], __ldg(&cn[gn]));
                            if (dv < bv) { bv = dv; bi = gn; }
                        }
                    }
#pragma unroll
                    for (int off = 1; off < 4; off <<= 1) {
                        float ov = __shfl_xor_sync(0xffffffffu, bv, off);
                        int   oi = __shfl_xor_sync(0xffffffffu, bi, off);
                        if (ov < bv || (ov == bv && oi < bi)) { bv = ov; bi = oi; }
                    }
                    if ((lane & 3) == 0)
                        sMin[row * 2 + warp_n] = make_float2(bv, (float)bi);
                }
            }
            __syncthreads();
            if (tid < HM) {
                float2 c0 = sMin[tid * 2 + 0], c1 = sMin[tid * 2 + 1];
                float2 b = (c1.x < c0.x || (c1.x == c0.x && c1.y < c0.y)) ? c1 : c0;
                ((float2*)Cout)[(size_t)(m0 + tid) * 2 + blockIdx.x] = b;
            }
        } else {
            int colbase = n0 - 256;
#pragma unroll
            for (int im = 0; im < 2; im++) {
#pragma unroll
                for (int h = 0; h < 2; h++) {
                    int gm = m0 + warp_m * 32 + im * 16 + qr + h * 8;
#pragma unroll
                    for (int jn = 0; jn < NT; jn++) {
                        int col = colbase + warp_n * (NT * 8) + jn * 8 + qc;
                        *(float2*)((float*)Cout2 + (size_t)gm * 256 + col) =
                            make_float2(acc[im][jn][h * 2 + 0],
                                        acc[im][jn][h * 2 + 1]);
                    }
                }
            }
        }
        return;
    }

    float lsum = 0.f;
#pragma unroll
    for (int im = 0; im < 2; im++) {
#pragma unroll
        for (int h = 0; h < 2; h++) {
            int gm = m0 + warp_m * 32 + im * 16 + qr + h * 8;
#pragma unroll
            for (int jn = 0; jn < NT; jn++) {
                int gn = n0 + warp_n * (NT * 8) + jn * 8 + qc;
                float v0 = acc[im][jn][h * 2 + 0];
                float v1 = acc[im][jn][h * 2 + 1];
                if (EPI == 1) {
                    v0 = fmaxf(v0 + __ldg(&aux[gn]),     0.f);
                    v1 = fmaxf(v1 + __ldg(&aux[gn + 1]), 0.f);
                    bf16 h0, l0, h1, l1;
                    split_bf16(v0, h0, l0); split_bf16(v1, h1, l1);
                    bf16* Cr = (bf16*)Cout + (size_t)gm * ldc;
                    bf162 hp; hp.x = h0; hp.y = h1;
                    bf162 lp; lp.x = l0; lp.y = l1;
                    *(bf162*)(Cr + gn)        = hp;
                    *(bf162*)(Cr + Nout + gn) = lp;
                } else if (EPI == 2) {
                    v0 = tanhf(v0 + __ldg(&aux[gn]));
                    v1 = tanhf(v1 + __ldg(&aux[gn + 1]));
                    const float* Xr = X + (size_t)gm * Nout + gn;
                    float d0 = v0 - Xr[0], d1 = v1 - Xr[1];
                    lsum = fmaf(d0, d0, fmaf(d1, d1, lsum));
                    *(float2*)((float*)Cout + (size_t)gm * Nout + gn) =
                        make_float2(v0, v1);
                } else {  // EPI == 3
                    v0 += __ldg(&aux[gn]);
                    v1 += __ldg(&aux[gn + 1]);
                    *(float2*)((float*)Cout + (size_t)gm * Nout + gn) =
                        make_float2(v0, v1);
                    bf16 h0, l0, h1, l1;
                    split_bf16(v0, h0, l0); split_bf16(v1, h1, l1);
                    bf16* Cr = (bf16*)Cout2 + (size_t)gm * (2 * Nout);
                    bf162 hp; hp.x = h0; hp.y = h1;
                    bf162 lp; lp.x = l0; lp.y = l1;
                    *(bf162*)(Cr + gn)        = hp;
                    *(bf162*)(Cr + Nout + gn) = lp;
                }
            }
        }
    }

    if (EPI == 2) {
#pragma unroll
        for (int off = 16; off > 0; off >>= 1)
            lsum += __shfl_down_sync(0xffffffffu, lsum, off);
        if (lane == 0) red[wid] = lsum;
        __syncthreads();
        if (tid == 0) {
            float s = 0.f;
#pragma unroll
            for (int i = 0; i < 8; i++) s += red[i];
            atomicAdd(lossAcc, (double)s);
        }
    }
}

// ------------- combined VQ: argmin0 + argmin1 + commits + dec1 gather -------
__global__ void __launch_bounds__(256)
vq_k(const float2* __restrict__ Sp, const float* __restrict__ S1e,
     const float* __restrict__ T1, const float* __restrict__ enc,
     const float* __restrict__ P0, const float* __restrict__ P1,
     const float* __restrict__ bd1, __half* __restrict__ dout,
     float* __restrict__ idx_out, double* __restrict__ lossBase) {
    __shared__ float w0s[8], w1s[8];
    int warp = threadIdx.x >> 5, lane = threadIdx.x & 31;
    size_t m = (size_t)blockIdx.x * 8 + warp;

    float2 a0 = Sp[m * 2 + 0];
    float2 a1 = Sp[m * 2 + 1];
    float2 b0 = (a1.x < a0.x || (a1.x == a0.x && a1.y < a0.y)) ? a1 : a0;
    int i0 = (int)b0.y;
    float dmin0 = b0.x;

    const float* T1r = T1 + (size_t)i0 * N_CODES;
    const float* S1r = S1e + m * N_CODES;
    float bv = 3.4e38f; int bi = 0x7fffffff;
#pragma unroll
    for (int t = 0; t < 8; t++) {
        int j = t * 32 + lane;
        float dv = fmaf(-2.f, S1r[j], T1r[j]);
        if (dv < bv) { bv = dv; bi = j; }
    }
#pragma unroll
    for (int off = 16; off > 0; off >>= 1) {
        float ov = __shfl_down_sync(0xffffffffu, bv, off);
        int   oi = __shfl_down_sync(0xffffffffu, bi, off);
        if (ov < bv || (ov == bv && oi < bi)) { bv = ov; bi = oi; }
    }
    bi = __shfl_sync(0xffffffffu, bi, 0);
    bv = __shfl_sync(0xffffffffu, bv, 0);
    int i1 = bi;

    const float4* e4 = (const float4*)(enc + m * D_LAT);
    float4 u = e4[lane * 2], v = e4[lane * 2 + 1];
    float ss = u.x * u.x + u.y * u.y + u.z * u.z + u.w * u.w
             + v.x * v.x + v.y * v.y + v.z * v.z + v.w * v.w;
#pragma unroll
    for (int off = 16; off > 0; off >>= 1)
        ss += __shfl_down_sync(0xffffffffu, ss, off);

    if (lane == 0) {
        idx_out[m * 2 + 0] = (float)i0;
        idx_out[m * 2 + 1] = (float)i1;
        float c0v = ss + dmin0;
        w0s[warp] = c0v;
        w1s[warp] = c0v + bv;
    }

    const float4* p0 = (const float4*)(P0 + (size_t)i0 * D_HID);
    const float4* p1 = (const float4*)(P1 + (size_t)i1 * D_HID);
    const float4* bz = (const float4*)bd1;
    __half2* dd = (__half2*)(dout + m * D_HID);
#pragma unroll
    for (int t = 0; t < 4; t++) {
        int n4 = t * 32 + lane;
        float4 xa = p0[n4], xb = p1[n4], xc = __ldg(&bz[n4]);
        float r0 = fmaxf(xa.x + xb.x + xc.x, 0.f);
        float r1 = fmaxf(xa.y + xb.y + xc.y, 0.f);
        float r2 = fmaxf(xa.z + xb.z + xc.z, 0.f);
        float r3 = fmaxf(xa.w + xb.w + xc.w, 0.f);
        __half2 h0; h0.x = __float2half_rn(r0); h0.y = __float2half_rn(r1);
        __half2 h1; h1.x = __float2half_rn(r2); h1.y = __float2half_rn(r3);
        dd[n4 * 2 + 0] = h0;
        dd[n4 * 2 + 1] = h1;
    }

    __syncthreads();
    if (threadIdx.x == 0) {
        float s0 = 0.f, s1 = 0.f;
#pragma unroll
        for (int i = 0; i < 8; i++) { s0 += w0s[i]; s1 += w1s[i]; }
        atomicAdd(lossBase + 1, (double)s0);
        atomicAdd(lossBase + 2, (double)s1);
    }
}

// ---------------- launch ----------------------------------------------------
extern "C" void kernel_launch(void* const* d_in, const int* in_sizes, int n_in,
                              void* d_out, int out_size) {
    const float* x   = (const float*)d_in[0];
    const float* We1 = (const float*)d_in[1];
    const float* be1 = (const float*)d_in[2];
    const float* We2 = (const float*)d_in[3];
    const float* be2 = (const float*)d_in[4];
    const float* cb0 = (const float*)d_in[5];
    const float* cb1 = (const float*)d_in[6];
    const float* Wd1 = (const float*)d_in[7];
    const float* bd1 = (const float*)d_in[8];
    const float* Wd2 = (const float*)d_in[9];
    const float* bd2 = (const float*)d_in[10];

    float* out       = (float*)d_out;
    float* out_recon = out;
    float* out_idx   = out + (size_t)B_ROWS * D_IN;
    float* out_loss  = out + (size_t)B_ROWS * D_IN + (size_t)B_ROWS * 2;

    bf16 *px3, *ph3, *pe3, *pWe1b, *pWe2b, *pcb3;
    __half *pd1, *pW2b;
    float *penc, *pcn, *pS1, *pT1, *pP0, *pP1;
    float2* pSp;
    double* pl;
    cudaGetSymbolAddress((void**)&px3,   g_x3);
    cudaGetSymbolAddress((void**)&ph3,   g_h3);
    cudaGetSymbolAddress((void**)&penc,  g_enc);
    cudaGetSymbolAddress((void**)&pe3,   g_e3);
    cudaGetSymbolAddress((void**)&pSp,   g_Sp);
    cudaGetSymbolAddress((void**)&pS1,   g_S1);
    cudaGetSymbolAddress((void**)&pd1,   g_d1);
    cudaGetSymbolAddress((void**)&pWe1b, g_We1b);
    cudaGetSymbolAddress((void**)&pWe2b, g_We2b);
    cudaGetSymbolAddress((void**)&pcb3,  g_cb3);
    cudaGetSymbolAddress((void**)&pW2b,  g_W2b);
    cudaGetSymbolAddress((void**)&pcn,   g_cnorm);
    cudaGetSymbolAddress((void**)&pT1,   g_T1);
    cudaGetSymbolAddress((void**)&pP0,   g_P0);
    cudaGetSymbolAddress((void**)&pP1,   g_P1);
    cudaGetSymbolAddress((void**)&pl,    g_loss);

    cudaFuncSetAttribute((const void*)hmma_k<1, 8, 0>, cudaFuncAttributeMaxDynamicSharedMemorySize, SMEM_HMMA);
    cudaFuncSetAttribute((const void*)hmma_k<3, 8, 0>, cudaFuncAttributeMaxDynamicSharedMemorySize, SMEM_HMMA);
    cudaFuncSetAttribute((const void*)hmma_k<4, 8, 0>, cudaFuncAttributeMaxDynamicSharedMemorySize, SMEM_HMMA);
    cudaFuncSetAttribute((const void*)hmma_k<2, 7, 1>, cudaFuncAttributeMaxDynamicSharedMemorySize, SMEM_HMMA);

    dim3 blk(256);

    init_k<<<1, 32>>>();
    prep_x_k<<<(int)(((size_t)B_ROWS * (D_IN / 4) + 255) / 256), 256>>>(x);
    prep_we1_k<<<(D_HID * D_IN + 255) / 256, 256>>>(We1);
    prep_small_k<<<NB_WE2 + NB_WD2, 256>>>(We2, Wd2);
    prep_cb_k<<<512, 256>>>(cb0, cb1);
    prep_T1_k<<<32, 256>>>(cb0);
    prep_P_k<<<64, 512>>>(cb0, cb1, Wd1);

    // encoder GEMM1: triple-stored A (kA == K, no remap), K = 2368
    hmma_k<1, 8, 0><<<dim3(D_HID / 128, B_ROWS / HM), blk, SMEM_HMMA>>>(
        px3, pWe1b, be1, ph3, nullptr, KB_XC, KB_XC, D_HID, KA_H, nullptr, nullptr);
    hmma_k<3, 8, 0><<<dim3(D_LAT / 128, B_ROWS / HM), blk, SMEM_HMMA>>>(
        ph3, pWe2b, be2, penc, pe3, KA_H, KB_H, D_LAT, 0, nullptr, nullptr);

    // combined score GEMM over [cb0|cb1]: argmin blocks + raw S1
    hmma_k<4, 8, 0><<<dim3(512 / 128, B_ROWS / HM), blk, SMEM_HMMA>>>(
        pe3, pcb3, pcn, pSp, pS1, KA_E, KB_E, 512, 0, nullptr, nullptr);

    // combined VQ + dec1 gather
    vq_k<<<B_ROWS / 8, 256>>>(pSp, pS1, pT1, penc, pP0, pP1, bd1,
                              pd1, out_idx, pl);

    // dec2 (fp16-1)
    hmma_k<2, 7, 1><<<dim3(D_IN / 112, B_ROWS / HM), blk, SMEM_HMMA>>>(
        pd1, pW2b, bd2, out_recon, nullptr, D_HID, D_HID, D_IN, 0, x, pl + 0);

    finalize_k<<<1, 1>>>(out_loss);
}

// round 15
// speedup vs baseline: 1.1252x; 1.0144x over previous
#include <cuda_runtime.h>
#include <cuda_bf16.h>
#include <cuda_fp16.h>
#include <cstdint>
#include <math.h>

#define B_ROWS 65536
#define D_IN   784
#define D_HID  512
#define D_LAT  256
#define N_CODES 256
#define N_PAD  896
#define KB_XC  2368           // [xh|xl|xh|pad16] : 3*784=2352 padded to 37*64
#define KA_H   (2 * D_HID)    // 1024
#define KB_H   (3 * D_HID)    // 1536
#define KA_E   (2 * D_LAT)    // 512
#define KB_E   (3 * D_LAT)    // 768

typedef __nv_bfloat16 bf16;
typedef __nv_bfloat162 bf162;

// ---------------- scratch ----------------------------------------------------
__device__ bf16 g_x3 [(size_t)B_ROWS * KB_XC];   // [xh|xl|xh|0]
__device__ bf16 g_h3 [(size_t)B_ROWS * KA_H];    // [hh|hl]
__device__ bf16 g_e3 [(size_t)B_ROWS * KA_E];    // [eh|el]
__device__ float g_sq2[(size_t)B_ROWS * 2];      // per-block row sumsq of enc
__device__ float2 g_Sp[(size_t)B_ROWS * 2];      // cb0 block argmins
__device__ float g_S1[(size_t)B_ROWS * N_CODES]; // raw enc.cb1^T
__device__ __half g_d1[(size_t)B_ROWS * D_HID];  // decoder hidden fp16
__device__ bf16 g_We1b[(size_t)D_HID * KB_XC];   // [Wh|Wh|Wl|pad16]
__device__ bf16 g_We2b[(size_t)D_LAT * KB_H];
__device__ bf16 g_cb3 [2 * N_CODES * KB_E];      // [cb0 rows | cb1 rows]
__device__ __half g_W2b[(size_t)N_PAD * D_HID];  // Wd2^T fp16
__device__ float g_cnorm[2 * N_CODES];
__device__ float g_cb1T[N_CODES * D_LAT];
__device__ float g_T1 [N_CODES * N_CODES];       // cn1[j] + 2*cb0_i.cb1_j
__device__ float g_P0 [N_CODES * D_HID];         // cb0 @ Wd1
__device__ float g_P1 [N_CODES * D_HID];         // cb1 @ Wd1
__device__ double g_loss[3];

// ====================== PTX helpers ========================================
__device__ __forceinline__ uint32_t smem_u32(const void* p) {
    uint32_t a;
    asm("{ .reg .u64 t; cvta.to.shared.u64 t, %1; cvt.u32.u64 %0, t; }"
        : "=r"(a) : "l"(p));
    return a;
}
#define CP16(dst, src) \
    asm volatile("cp.async.cg.shared.global [%0], [%1], 16;" :: "r"(dst), "l"(src) : "memory")
#define CP_COMMIT() asm volatile("cp.async.commit_group;" ::: "memory")
#define CP_WAIT(n)  asm volatile("cp.async.wait_group %0;" :: "n"(n) : "memory")

__device__ __forceinline__ void ldsm_x4(uint32_t* r, uint32_t addr) {
    asm volatile("ldmatrix.sync.aligned.m8n8.x4.shared.b16 {%0,%1,%2,%3}, [%4];"
        : "=r"(r[0]), "=r"(r[1]), "=r"(r[2]), "=r"(r[3]) : "r"(addr));
}
__device__ __forceinline__ void ldsm_x2(uint32_t* r, uint32_t addr) {
    asm volatile("ldmatrix.sync.aligned.m8n8.x2.shared.b16 {%0,%1}, [%2];"
        : "=r"(r[0]), "=r"(r[1]) : "r"(addr));
}
__device__ __forceinline__ void mma_bf16(float* c, const uint32_t* a, const uint32_t* b) {
    asm volatile("mma.sync.aligned.m16n8k16.row.col.f32.bf16.bf16.f32 "
        "{%0,%1,%2,%3}, {%4,%5,%6,%7}, {%8,%9}, {%0,%1,%2,%3};"
        : "+f"(c[0]), "+f"(c[1]), "+f"(c[2]), "+f"(c[3])
        : "r"(a[0]), "r"(a[1]), "r"(a[2]), "r"(a[3]), "r"(b[0]), "r"(b[1]));
}
__device__ __forceinline__ void mma_f16(float* c, const uint32_t* a, const uint32_t* b) {
    asm volatile("mma.sync.aligned.m16n8k16.row.col.f32.f16.f16.f32 "
        "{%0,%1,%2,%3}, {%4,%5,%6,%7}, {%8,%9}, {%0,%1,%2,%3};"
        : "+f"(c[0]), "+f"(c[1]), "+f"(c[2]), "+f"(c[3])
        : "r"(a[0]), "r"(a[1]), "r"(a[2]), "r"(a[3]), "r"(b[0]), "r"(b[1]));
}
__device__ __forceinline__ void split_bf16(float v, bf16& hi, bf16& lo) {
    hi = __float2bfloat16_rn(v);
    lo = __float2bfloat16_rn(v - __bfloat162float(hi));
}

// ---------------- prep kernels ---------------------------------------------
__global__ void init_k() {
    if (threadIdx.x < 3) g_loss[threadIdx.x] = 0.0;
}

// x [B,784] f32 -> g_x3 [B,2368] = [xh|xl|xh|0]; 8-elem granules, 16B stores
__global__ void prep_x_k(const float* __restrict__ x) {
    size_t idx = (size_t)blockIdx.x * blockDim.x + threadIdx.x;
    if (idx >= (size_t)B_ROWS * (D_IN / 8)) return;
    size_t m = idx / (D_IN / 8);
    int g = (int)(idx % (D_IN / 8));              // 0..97
    const float4* xr = (const float4*)(x + m * D_IN + g * 8);
    float4 a = __ldg(xr), b = __ldg(xr + 1);
    float vv[8] = {a.x, a.y, a.z, a.w, b.x, b.y, b.z, b.w};
    uint32_t hw[4], lw[4];
#pragma unroll
    for (int e = 0; e < 4; e++) {
        bf16 h0, l0, h1, l1;
        split_bf16(vv[2 * e], h0, l0);
        split_bf16(vv[2 * e + 1], h1, l1);
        bf162 hp; hp.x = h0; hp.y = h1;
        bf162 lp; lp.x = l0; lp.y = l1;
        hw[e] = *(uint32_t*)&hp;
        lw[e] = *(uint32_t*)&lp;
    }
    bf16* R = g_x3 + m * KB_XC;
    uint4 hq = make_uint4(hw[0], hw[1], hw[2], hw[3]);
    uint4 lq = make_uint4(lw[0], lw[1], lw[2], lw[3]);
    *(uint4*)(R + g * 8)              = hq;
    *(uint4*)(R + D_IN + g * 8)       = lq;
    *(uint4*)(R + 2 * D_IN + g * 8)   = hq;
    if (g == 0) {  // zero 16-elem pad
        uint4 z = make_uint4(0u, 0u, 0u, 0u);
        *(uint4*)(R + 2352) = z;
        *(uint4*)(R + 2360) = z;
    }
}

// We1 [784,512] -> g_We1b [512, 2368] rows [Wh|Wh|Wl|0]
__global__ void prep_we1_k(const float* __restrict__ We1) {
    int idx = blockIdx.x * blockDim.x + threadIdx.x;
    if (idx < D_HID * D_IN) {
        int n = idx / D_IN, k = idx % D_IN;
        bf16 hi, lo; split_bf16(We1[(size_t)k * D_HID + n], hi, lo);
        bf16* R = g_We1b + (size_t)n * KB_XC;
        R[k] = hi; R[D_IN + k] = hi; R[2 * D_IN + k] = lo;
        if (k < 16) R[2352 + k] = __float2bfloat16(0.f);
    }
}

// merged: We2 bf16-3 (512 blocks) | Wd2 fp16-1 (1792 blocks)
#define NB_WE2 (D_LAT * D_HID / 256)     // 512
#define NB_WD2 (N_PAD * D_HID / 256)     // 1792
__global__ void prep_small_k(const float* __restrict__ We2,
                             const float* __restrict__ Wd2) {
    int b = blockIdx.x;
    if (b < NB_WE2) {
        int idx = b * 256 + threadIdx.x;
        int n = idx / D_HID, k = idx % D_HID;
        bf16 hi, lo; split_bf16(We2[(size_t)k * D_LAT + n], hi, lo);
        bf16* R = g_We2b + (size_t)n * KB_H;
        R[k] = hi; R[D_HID + k] = hi; R[2 * D_HID + k] = lo;
        return;
    }
    b -= NB_WE2;
    {
        int idx = b * 256 + threadIdx.x;
        int n = idx / D_HID, k = idx % D_HID;
        g_W2b[(size_t)n * D_HID + k] =
            (n < D_IN) ? __float2half_rn(Wd2[(size_t)k * D_IN + n])
                       : __float2half_rn(0.f);
    }
}

// codebooks -> g_cb3 (split) + cnorm + cb1 transpose
__global__ void prep_cb_k(const float* __restrict__ cb0,
                          const float* __restrict__ cb1) {
    __shared__ float red[8];
    int c = blockIdx.x >> 8;
    int n = blockIdx.x & 255;
    int k = threadIdx.x;
    const float* cb = c ? cb1 : cb0;
    float v = cb[(size_t)n * D_LAT + k];
    bf16 hi, lo; split_bf16(v, hi, lo);
    bf16* R = g_cb3 + ((size_t)c * N_CODES + n) * KB_E;
    R[k] = hi; R[D_LAT + k] = hi; R[2 * D_LAT + k] = lo;
    if (c) g_cb1T[k * N_CODES + n] = v;

    float s = v * v;
    int lane = k & 31, warp = k >> 5;
#pragma unroll
    for (int off = 16; off > 0; off >>= 1)
        s += __shfl_down_sync(0xffffffffu, s, off);
    if (lane == 0) red[warp] = s;
    __syncthreads();
    if (k == 0) {
        float t = 0.f;
#pragma unroll
        for (int i = 0; i < 8; i++) t += red[i];
        g_cnorm[c * N_CODES + n] = t;
    }
}

// T1[i,j] = cn1[j] + 2*dot(cb0_i, cb1_j)
__global__ void prep_T1_k(const float* __restrict__ cb0) {
    __shared__ float c0s[8][256];
    int j = threadIdx.x;
    int i0 = blockIdx.x * 8;
#pragma unroll
    for (int ii = 0; ii < 8; ii++)
        c0s[ii][j] = cb0[(size_t)(i0 + ii) * D_LAT + j];
    __syncthreads();
    float acc[8] = {0, 0, 0, 0, 0, 0, 0, 0};
    for (int k = 0; k < D_LAT; k++) {
        float bvv = g_cb1T[k * N_CODES + j];
#pragma unroll
        for (int ii = 0; ii < 8; ii++) acc[ii] = fmaf(c0s[ii][k], bvv, acc[ii]);
    }
    float cn1 = g_cnorm[N_CODES + j];
#pragma unroll
    for (int ii = 0; ii < 8; ii++)
        g_T1[(size_t)(i0 + ii) * N_CODES + j] = fmaf(2.f, acc[ii], cn1);
}

// P[i,n] = dot(cb_i, Wd1[:,n])
__global__ void prep_P_k(const float* __restrict__ cb0,
                         const float* __restrict__ cb1,
                         const float* __restrict__ Wd1) {
    __shared__ float cs[8][256];
    int cbi = blockIdx.x >> 5;
    int i0 = (blockIdx.x & 31) * 8;
    const float* cb = cbi ? cb1 : cb0;
    float* P = cbi ? g_P1 : g_P0;
    int tid = threadIdx.x;
#pragma unroll
    for (int t = 0; t < 4; t++) {
        int u = tid + t * 512;
        cs[u >> 8][u & 255] = cb[(size_t)(i0 + (u >> 8)) * D_LAT + (u & 255)];
    }
    __syncthreads();
    float acc[8] = {0, 0, 0, 0, 0, 0, 0, 0};
    for (int k = 0; k < D_LAT; k++) {
        float w = Wd1[(size_t)k * D_HID + tid];
#pragma unroll
        for (int ii = 0; ii < 8; ii++) acc[ii] = fmaf(cs[ii][k], w, acc[ii]);
    }
#pragma unroll
    for (int ii = 0; ii < 8; ii++)
        P[(size_t)(i0 + ii) * D_HID + tid] = acc[ii];
}

__global__ void finalize_k(float* __restrict__ out_loss) {
    double loss = g_loss[0] / ((double)B_ROWS * (double)D_IN)
                + 0.25 * ((g_loss[1] + g_loss[2]) / ((double)B_ROWS * (double)D_LAT));
    out_loss[0] = (float)loss;
}

// ---------------- universal split HMMA GEMM (3-stage pipeline) --------------
// C[M,N] = A[M,kA] @ BT[N,K]^T, K-remap on A (wraps when K > kA).
// EPI 1: +bias, relu -> bf16 split pair [h|l], row stride ldc
// EPI 2: +bias, tanh -> f32 store + sum((v-X)^2) into lossAcc
// EPI 3: +bias -> bf16 split pair (Cout2, 2*Nout) + per-row sumsq partials
//        into Cout float[m*2 + blockIdx.x]
// EPI 4: N=512 scores: blocks 0,1 argmin -> Cout; blocks 2,3 raw -> Cout2
#define HM 128
#define HK 64
#define PITCH 144
#define NSTAGE 3
#define TILE_B (HM * PITCH)
#define SMEM_HMMA (2 * NSTAGE * TILE_B)

template <int EPI, int NT, int DT>
__global__ void __launch_bounds__(256)
hmma_k(const void* __restrict__ Av, const void* __restrict__ BTv,
       const float* __restrict__ aux, void* __restrict__ Cout,
       void* __restrict__ Cout2, int kA, int K, int Nout, int ldc,
       const float* __restrict__ X, double* __restrict__ lossAcc) {
    extern __shared__ char sm[];
    __shared__ float red[8];

    const int HN_T = 16 * NT;
    const int tid = threadIdx.x;
    const int wid = tid >> 5, lane = tid & 31;
    const int warp_m = wid >> 1, warp_n = wid & 1;
    const int m0 = blockIdx.y * HM, n0 = blockIdx.x * HN_T;
    const int NC = K / HK;

    const uint32_t smA = smem_u32(sm);
    const uint32_t smB = smA + NSTAGE * TILE_B;

    const int lrow = tid >> 3;
    const int lseg = (tid & 7) << 4;
    const size_t rsA = (size_t)kA * 2;
    const size_t rsB = (size_t)K * 2;
    const char* Ag = (const char*)Av + (size_t)m0 * rsA + (size_t)lrow * rsA + lseg;
    const char* Bg = (const char*)BTv + (size_t)n0 * rsB + (size_t)lrow * rsB + lseg;
    const uint32_t stoff = lrow * PITCH + lseg;
    const int kAb = kA * 2;

    const int a_row = (lane & 15);
    const int a_kb16 = (lane >> 4) << 4;
    const int b_row = (lane & 7) + ((lane >> 4) << 3);
    const int b_kb16 = ((lane >> 3) & 1) << 4;

    uint32_t a_sm[NSTAGE], b_sm[NSTAGE];
#pragma unroll
    for (int s = 0; s < NSTAGE; s++) {
        a_sm[s] = smA + s * TILE_B + (warp_m * 32 + a_row) * PITCH + a_kb16;
        b_sm[s] = smB + s * TILE_B + (warp_n * (NT * 8) + b_row) * PITCH + b_kb16;
    }

    float acc[2][NT][4];
#pragma unroll
    for (int i = 0; i < 2; i++)
#pragma unroll
        for (int j = 0; j < NT; j++)
#pragma unroll
            for (int t = 0; t < 4; t++) acc[i][j][t] = 0.f;

#pragma unroll
    for (int s = 0; s < NSTAGE - 1; s++) {
        int koffB = s * (HK * 2);
        int koffA = (koffB < kAb) ? koffB : koffB - kAb;
        uint32_t ast = smA + s * TILE_B + stoff;
        uint32_t bst = smB + s * TILE_B + stoff;
#pragma unroll
        for (int j = 0; j < 4; j++) {
            CP16(ast + j * 32 * PITCH, Ag + (size_t)j * 32 * rsA + koffA);
            CP16(bst + j * 32 * PITCH, Bg + (size_t)j * 32 * rsB + koffB);
        }
        CP_COMMIT();
    }

    int pf = NSTAGE - 1;
    for (int i = 0; i < NC; i++) {
        CP_WAIT(NSTAGE - 2);
        __syncthreads();

        if (pf < NC) {
            int buf = pf % NSTAGE;
            int koffB = pf * (HK * 2);
            int koffA = (koffB < kAb) ? koffB : koffB - kAb;
            uint32_t ast = smA + buf * TILE_B + stoff;
            uint32_t bst = smB + buf * TILE_B + stoff;
#pragma unroll
            for (int j = 0; j < 4; j++) {
                CP16(ast + j * 32 * PITCH, Ag + (size_t)j * 32 * rsA + koffA);
                CP16(bst + j * 32 * PITCH, Bg + (size_t)j * 32 * rsB + koffB);
            }
        }
        CP_COMMIT();
        pf++;

        int buf = i % NSTAGE;
#pragma unroll
        for (int ks = 0; ks < 4; ks++) {
            uint32_t af[2][4];
#pragma unroll
            for (int im = 0; im < 2; im++)
                ldsm_x4(af[im], a_sm[buf] + im * 16 * PITCH + ks * 32);
            uint32_t bfr[(NT + 1) / 2][4];
#pragma unroll
            for (int jp = 0; jp < NT / 2; jp++)
                ldsm_x4(bfr[jp], b_sm[buf] + jp * 16 * PITCH + ks * 32);
            if (NT & 1)
                ldsm_x2(bfr[NT / 2], b_sm[buf] + (NT - 1) * 8 * PITCH + ks * 32);
#pragma unroll
            for (int im = 0; im < 2; im++)
#pragma unroll
                for (int jn = 0; jn < NT; jn++) {
                    if (DT == 0)
                        mma_bf16(acc[im][jn], af[im], &bfr[jn >> 1][(jn & 1) * 2]);
                    else
                        mma_f16(acc[im][jn], af[im], &bfr[jn >> 1][(jn & 1) * 2]);
                }
        }
    }

    // ---- epilogue
    const int qr = lane >> 2, qc = (lane & 3) * 2;

    if (EPI == 3) {
        __syncthreads();                   // smem now reusable as sSq
        float* sSq = (float*)sm;           // [128][2]
#pragma unroll
        for (int im = 0; im < 2; im++) {
#pragma unroll
            for (int h = 0; h < 2; h++) {
                int row = warp_m * 32 + im * 16 + h * 8 + qr;
                int gm = m0 + row;
                float rs = 0.f;
#pragma unroll
                for (int jn = 0; jn < NT; jn++) {
                    int gn = n0 + warp_n * (NT * 8) + jn * 8 + qc;
                    float v0 = acc[im][jn][h * 2 + 0] + __ldg(&aux[gn]);
                    float v1 = acc[im][jn][h * 2 + 1] + __ldg(&aux[gn + 1]);
                    rs = fmaf(v0, v0, fmaf(v1, v1, rs));
                    bf16 h0, l0, h1, l1;
                    split_bf16(v0, h0, l0); split_bf16(v1, h1, l1);
                    bf16* Cr = (bf16*)Cout2 + (size_t)gm * (2 * Nout);
                    bf162 hp; hp.x = h0; hp.y = h1;
                    bf162 lp; lp.x = l0; lp.y = l1;
                    *(bf162*)(Cr + gn)        = hp;
                    *(bf162*)(Cr + Nout + gn) = lp;
                }
                rs += __shfl_xor_sync(0xffffffffu, rs, 1);
                rs += __shfl_xor_sync(0xffffffffu, rs, 2);
                if ((lane & 3) == 0) sSq[row * 2 + warp_n] = rs;
            }
        }
        __syncthreads();
        if (tid < HM)
            ((float*)Cout)[(size_t)(m0 + tid) * 2 + blockIdx.x] =
                sSq[tid * 2 + 0] + sSq[tid * 2 + 1];
        return;
    }

    if (EPI == 4) {
        if (blockIdx.x < 2) {
            __syncthreads();
            float2* sMin = (float2*)sm;
            const float* cn = aux;
#pragma unroll
            for (int im = 0; im < 2; im++) {
#pragma unroll
                for (int h = 0; h < 2; h++) {
                    int row = warp_m * 32 + im * 16 + h * 8 + qr;
                    float bv = 3.4e38f; int bi = 0x7fffffff;
#pragma unroll
                    for (int jn = 0; jn < NT; jn++) {
#pragma unroll
                        for (int t = 0; t < 2; t++) {
                            int gn = n0 + warp_n * (NT * 8) + jn * 8 + qc + t;
                            float dv = fmaf(-2.f, acc[im][jn][h * 2 + t], __ldg(&cn[gn]));
                            if (dv < bv) { bv = dv; bi = gn; }
                        }
                    }
#pragma unroll
                    for (int off = 1; off < 4; off <<= 1) {
                        float ov = __shfl_xor_sync(0xffffffffu, bv, off);
                        int   oi = __shfl_xor_sync(0xffffffffu, bi, off);
                        if (ov < bv || (ov == bv && oi < bi)) { bv = ov; bi = oi; }
                    }
                    if ((lane & 3) == 0)
                        sMin[row * 2 + warp_n] = make_float2(bv, (float)bi);
                }
            }
            __syncthreads();
            if (tid < HM) {
                float2 c0 = sMin[tid * 2 + 0], c1 = sMin[tid * 2 + 1];
                float2 b = (c1.x < c0.x || (c1.x == c0.x && c1.y < c0.y)) ? c1 : c0;
                ((float2*)Cout)[(size_t)(m0 + tid) * 2 + blockIdx.x] = b;
            }
        } else {
            int colbase = n0 - 256;
#pragma unroll
            for (int im = 0; im < 2; im++) {
#pragma unroll
                for (int h = 0; h < 2; h++) {
                    int gm = m0 + warp_m * 32 + im * 16 + qr + h * 8;
#pragma unroll
                    for (int jn = 0; jn < NT; jn++) {
                        int col = colbase + warp_n * (NT * 8) + jn * 8 + qc;
                        *(float2*)((float*)Cout2 + (size_t)gm * 256 + col) =
                            make_float2(acc[im][jn][h * 2 + 0],
                                        acc[im][jn][h * 2 + 1]);
                    }
                }
            }
        }
        return;
    }

    float lsum = 0.f;
#pragma unroll
    for (int im = 0; im < 2; im++) {
#pragma unroll
        for (int h = 0; h < 2; h++) {
            int gm = m0 + warp_m * 32 + im * 16 + qr + h * 8;
#pragma unroll
            for (int jn = 0; jn < NT; jn++) {
                int gn = n0 + warp_n * (NT * 8) + jn * 8 + qc;
                float v0 = acc[im][jn][h * 2 + 0];
                float v1 = acc[im][jn][h * 2 + 1];
                if (EPI == 1) {
                    v0 = fmaxf(v0 + __ldg(&aux[gn]),     0.f);
                    v1 = fmaxf(v1 + __ldg(&aux[gn + 1]), 0.f);
                    bf16 h0, l0, h1, l1;
                    split_bf16(v0, h0, l0); split_bf16(v1, h1, l1);
                    bf16* Cr = (bf16*)Cout + (size_t)gm * ldc;
                    bf162 hp; hp.x = h0; hp.y = h1;
                    bf162 lp; lp.x = l0; lp.y = l1;
                    *(bf162*)(Cr + gn)        = hp;
                    *(bf162*)(Cr + Nout + gn) = lp;
                } else {  // EPI == 2
                    v0 = tanhf(v0 + __ldg(&aux[gn]));
                    v1 = tanhf(v1 + __ldg(&aux[gn + 1]));
                    const float* Xr = X + (size_t)gm * Nout + gn;
                    float d0 = v0 - Xr[0], d1 = v1 - Xr[1];
                    lsum = fmaf(d0, d0, fmaf(d1, d1, lsum));
                    *(float2*)((float*)Cout + (size_t)gm * Nout + gn) =
                        make_float2(v0, v1);
                }
            }
        }
    }

    if (EPI == 2) {
#pragma unroll
        for (int off = 16; off > 0; off >>= 1)
            lsum += __shfl_down_sync(0xffffffffu, lsum, off);
        if (lane == 0) red[wid] = lsum;
        __syncthreads();
        if (tid == 0) {
            float s = 0.f;
#pragma unroll
            for (int i = 0; i < 8; i++) s += red[i];
            atomicAdd(lossAcc, (double)s);
        }
    }
}

// ------------- combined VQ: argmin0 + argmin1 + commits + dec1 gather -------
__global__ void __launch_bounds__(256)
vq_k(const float2* __restrict__ Sp, const float* __restrict__ S1e,
     const float* __restrict__ T1, const float* __restrict__ sq2,
     const float* __restrict__ P0, const float* __restrict__ P1,
     const float* __restrict__ bd1, __half* __restrict__ dout,
     float* __restrict__ idx_out, double* __restrict__ lossBase) {
    __shared__ float w0s[8], w1s[8];
    int warp = threadIdx.x >> 5, lane = threadIdx.x & 31;
    size_t m = (size_t)blockIdx.x * 8 + warp;

    float2 a0 = Sp[m * 2 + 0];
    float2 a1 = Sp[m * 2 + 1];
    float2 b0 = (a1.x < a0.x || (a1.x == a0.x && a1.y < a0.y)) ? a1 : a0;
    int i0 = (int)b0.y;
    float dmin0 = b0.x;

    const float* T1r = T1 + (size_t)i0 * N_CODES;
    const float* S1r = S1e + m * N_CODES;
    float bv = 3.4e38f; int bi = 0x7fffffff;
#pragma unroll
    for (int t = 0; t < 8; t++) {
        int j = t * 32 + lane;
        float dv = fmaf(-2.f, S1r[j], T1r[j]);
        if (dv < bv) { bv = dv; bi = j; }
    }
#pragma unroll
    for (int off = 16; off > 0; off >>= 1) {
        float ov = __shfl_down_sync(0xffffffffu, bv, off);
        int   oi = __shfl_down_sync(0xffffffffu, bi, off);
        if (ov < bv || (ov == bv && oi < bi)) { bv = ov; bi = oi; }
    }
    bi = __shfl_sync(0xffffffffu, bi, 0);
    bv = __shfl_sync(0xffffffffu, bv, 0);
    int i1 = bi;

    if (lane == 0) {
        idx_out[m * 2 + 0] = (float)i0;
        idx_out[m * 2 + 1] = (float)i1;
        float ss = sq2[m * 2 + 0] + sq2[m * 2 + 1];   // ||enc||^2
        float c0v = ss + dmin0;
        w0s[warp] = c0v;
        w1s[warp] = c0v + bv;
    }

    const float4* p0 = (const float4*)(P0 + (size_t)i0 * D_HID);
    const float4* p1 = (const float4*)(P1 + (size_t)i1 * D_HID);
    const float4* bz = (const float4*)bd1;
    __half2* dd = (__half2*)(dout + m * D_HID);
#pragma unroll
    for (int t = 0; t < 4; t++) {
        int n4 = t * 32 + lane;
        float4 xa = p0[n4], xb = p1[n4], xc = __ldg(&bz[n4]);
        float r0 = fmaxf(xa.x + xb.x + xc.x, 0.f);
        float r1 = fmaxf(xa.y + xb.y + xc.y, 0.f);
        float r2 = fmaxf(xa.z + xb.z + xc.z, 0.f);
        float r3 = fmaxf(xa.w + xb.w + xc.w, 0.f);
        __half2 h0; h0.x = __float2half_rn(r0); h0.y = __float2half_rn(r1);
        __half2 h1; h1.x = __float2half_rn(r2); h1.y = __float2half_rn(r3);
        dd[n4 * 2 + 0] = h0;
        dd[n4 * 2 + 1] = h1;
    }

    __syncthreads();
    if (threadIdx.x == 0) {
        float s0 = 0.f, s1 = 0.f;
#pragma unroll
        for (int i = 0; i < 8; i++) { s0 += w0s[i]; s1 += w1s[i]; }
        atomicAdd(lossBase + 1, (double)s0);
        atomicAdd(lossBase + 2, (double)s1);
    }
}

// ---------------- launch ----------------------------------------------------
extern "C" void kernel_launch(void* const* d_in, const int* in_sizes, int n_in,
                              void* d_out, int out_size) {
    const float* x   = (const float*)d_in[0];
    const float* We1 = (const float*)d_in[1];
    const float* be1 = (const float*)d_in[2];
    const float* We2 = (const float*)d_in[3];
    const float* be2 = (const float*)d_in[4];
    const float* cb0 = (const float*)d_in[5];
    const float* cb1 = (const float*)d_in[6];
    const float* Wd1 = (const float*)d_in[7];
    const float* bd1 = (const float*)d_in[8];
    const float* Wd2 = (const float*)d_in[9];
    const float* bd2 = (const float*)d_in[10];

    float* out       = (float*)d_out;
    float* out_recon = out;
    float* out_idx   = out + (size_t)B_ROWS * D_IN;
    float* out_loss  = out + (size_t)B_ROWS * D_IN + (size_t)B_ROWS * 2;

    bf16 *px3, *ph3, *pe3, *pWe1b, *pWe2b, *pcb3;
    __half *pd1, *pW2b;
    float *pcn, *pS1, *pT1, *pP0, *pP1, *psq2;
    float2* pSp;
    double* pl;
    cudaGetSymbolAddress((void**)&px3,   g_x3);
    cudaGetSymbolAddress((void**)&ph3,   g_h3);
    cudaGetSymbolAddress((void**)&pe3,   g_e3);
    cudaGetSymbolAddress((void**)&psq2,  g_sq2);
    cudaGetSymbolAddress((void**)&pSp,   g_Sp);
    cudaGetSymbolAddress((void**)&pS1,   g_S1);
    cudaGetSymbolAddress((void**)&pd1,   g_d1);
    cudaGetSymbolAddress((void**)&pWe1b, g_We1b);
    cudaGetSymbolAddress((void**)&pWe2b, g_We2b);
    cudaGetSymbolAddress((void**)&pcb3,  g_cb3);
    cudaGetSymbolAddress((void**)&pW2b,  g_W2b);
    cudaGetSymbolAddress((void**)&pcn,   g_cnorm);
    cudaGetSymbolAddress((void**)&pT1,   g_T1);
    cudaGetSymbolAddress((void**)&pP0,   g_P0);
    cudaGetSymbolAddress((void**)&pP1,   g_P1);
    cudaGetSymbolAddress((void**)&pl,    g_loss);

    cudaFuncSetAttribute((const void*)hmma_k<1, 8, 0>, cudaFuncAttributeMaxDynamicSharedMemorySize, SMEM_HMMA);
    cudaFuncSetAttribute((const void*)hmma_k<3, 8, 0>, cudaFuncAttributeMaxDynamicSharedMemorySize, SMEM_HMMA);
    cudaFuncSetAttribute((const void*)hmma_k<4, 8, 0>, cudaFuncAttributeMaxDynamicSharedMemorySize, SMEM_HMMA);
    cudaFuncSetAttribute((const void*)hmma_k<2, 7, 1>, cudaFuncAttributeMaxDynamicSharedMemorySize, SMEM_HMMA);

    dim3 blk(256);

    init_k<<<1, 32>>>();
    prep_x_k<<<(int)(((size_t)B_ROWS * (D_IN / 8) + 255) / 256), 256>>>(x);
    prep_we1_k<<<(D_HID * D_IN + 255) / 256, 256>>>(We1);
    prep_small_k<<<NB_WE2 + NB_WD2, 256>>>(We2, Wd2);
    prep_cb_k<<<512, 256>>>(cb0, cb1);
    prep_T1_k<<<32, 256>>>(cb0);
    prep_P_k<<<64, 512>>>(cb0, cb1, Wd1);

    // encoder GEMM1: triple-stored A (kA == K, no remap), K = 2368
    hmma_k<1, 8, 0><<<dim3(D_HID / 128, B_ROWS / HM), blk, SMEM_HMMA>>>(
        px3, pWe1b, be1, ph3, nullptr, KB_XC, KB_XC, D_HID, KA_H, nullptr, nullptr);
    // GEMM2: emits e3 split pair + per-row ||enc||^2 partials (no f32 enc)
    hmma_k<3, 8, 0><<<dim3(D_LAT / 128, B_ROWS / HM), blk, SMEM_HMMA>>>(
        ph3, pWe2b, be2, psq2, pe3, KA_H, KB_H, D_LAT, 0, nullptr, nullptr);

    // combined score GEMM over [cb0|cb1]: argmin blocks + raw S1
    hmma_k<4, 8, 0><<<dim3(512 / 128, B_ROWS / HM), blk, SMEM_HMMA>>>(
        pe3, pcb3, pcn, pSp, pS1, KA_E, KB_E, 512, 0, nullptr, nullptr);

    // combined VQ + dec1 gather
    vq_k<<<B_ROWS / 8, 256>>>(pSp, pS1, pT1, psq2, pP0, pP1, bd1,
                              pd1, out_idx, pl);

    // dec2 (fp16-1)
    hmma_k<2, 7, 1><<<dim3(D_IN / 112, B_ROWS / HM), blk, SMEM_HMMA>>>(
        pd1, pW2b, bd2, out_recon, nullptr, D_HID, D_HID, D_IN, 0, x, pl + 0);

    finalize_k<<<1, 1>>>(out_loss);
}